// round 13
// baseline (speedup 1.0000x reference)
#include <cuda_runtime.h>
#include <cstdint>

#define B_    8
#define CIN_  128
#define H_    28
#define W_    28
#define COUT_ 256
#define NCB_  64
#define KC_   16
#define SUB_  18
#define NPIX_ 784
#define NTOT_ (B_ * NPIX_)   // 6272

// scratch (allocation-free rule: __device__ globals); 16B-aligned
__device__ __align__(16) int8_t  g_idx[NTOT_ * NCB_];           // idx[n][c], 401 KB
__device__ __align__(16) int16_t g_lut16[NCB_ * KC_ * COUT_];   // 512 KB

// ---- cp.async helpers (sm_100: LDGSTS) -----------------------------------
__device__ __forceinline__ void cp_async16(void* smem_dst, const void* gmem_src) {
    uint32_t d = (uint32_t)__cvta_generic_to_shared(smem_dst);
    asm volatile("cp.async.cg.shared.global [%0], [%1], 16;\n" :: "r"(d), "l"(gmem_src));
}
__device__ __forceinline__ void cp_commit() {
    asm volatile("cp.async.commit_group;\n");
}
__device__ __forceinline__ void cp_wait1() {
    asm volatile("cp.async.wait_group 1;\n");
}
__device__ __forceinline__ void cp_wait0() {
    asm volatile("cp.async.wait_group 0;\n");
}

// ---------------------------------------------------------------------------
// Kernel A (merged): blocks c < 64 do per-(codebook,batch) distances + argmin
// with INLINE y2r (bit-identical recipe); blocks c >= 64 do the lut
// int32 -> int16 repack. (unchanged from round-12 passing version)
// ---------------------------------------------------------------------------
__global__ void __launch_bounds__(256) idx_kernel(
    const int* __restrict__ xq, const int* __restrict__ xz_p,
    const int* __restrict__ cq, const int* __restrict__ cz_p,
    const float* __restrict__ cs, const float* __restrict__ xs,
    const int* __restrict__ lut_q)
{
    int c = blockIdx.x;   // codebook (or repack block if >= 64)
    int b = blockIdx.y;   // batch
    int tid = threadIdx.x;

    if (c >= NCB_) {      // ---- LUT repack: 64 blocks x 256 thr x 4 int4 ----
        int gid = ((c - NCB_) + 8 * b) * 256 + tid;   // [0, 16384)
        const int4* src = (const int4*)lut_q;         // 65536 int4
        uint2* dst = (uint2*)g_lut16;                 // 65536 uint2
        #pragma unroll
        for (int t = 0; t < 4; ++t) {
            int i = gid + t * 16384;
            int4 v = src[i];
            uint32_t lo = ((uint32_t)v.x & 0xFFFFu) | ((uint32_t)v.y << 16);
            uint32_t hi = ((uint32_t)v.z & 0xFFFFu) | ((uint32_t)v.w << 16);
            dst[i] = make_uint2(lo, hi);
        }
        return;
    }

    __shared__ int sx[2][30][32];   // halo window, (x_q - x_z), pad=0
    __shared__ int sc[KC_][SUB_];   // (c_q - c_z)
    __shared__ int sy[KC_];
    int xz = xz_p[0];
    int cz = cz_p[c];

    for (int t = tid; t < 1800; t += 256) {
        int cc  = t / 900;
        int r   = (t % 900) / 30;
        int col = t % 30;
        int ih = r - 1, iw = col - 1;
        int v = 0;
        if ((unsigned)ih < 28u && (unsigned)iw < 28u)
            v = xq[(((b * CIN_) + 2 * c + cc) * H_ + ih) * W_ + iw] - xz;
        sx[cc][r][col] = v;
    }
    for (int t = tid; t < KC_ * SUB_; t += 256)
        sc[t / SUB_][t % SUB_] = cq[c * KC_ * SUB_ + t] - cz;
    __syncthreads();

    // Inline y2r: (float)sc == (float)q - z exactly -> bit-identical recipe.
    if (tid < KC_) {
        float s = cs[c];
        float acc = 0.f;
        #pragma unroll
        for (int u = 0; u < SUB_; ++u) {
            float cv = __fmul_rn((float)sc[tid][u], s);
            acc = __fmaf_rn(cv, cv, acc);
        }
        sy[tid] = __float2int_rn(__fdiv_rn(acc, __fmul_rn(xs[0], s)));
    }
    __syncthreads();

    if (tid >= 196) return;           // 196 threads * 4 pixels = 784
    int p0  = tid * 4;                // 4|28 -> never crosses a row
    int oh  = tid / 7;
    int ow0 = (tid % 7) * 4;

    int w[2][3][6];                   // shared window of 4 adjacent pixels
    #pragma unroll
    for (int cc = 0; cc < 2; ++cc)
        #pragma unroll
        for (int i = 0; i < 3; ++i)
            #pragma unroll
            for (int col = 0; col < 6; ++col)
                w[cc][i][col] = sx[cc][oh + i][ow0 + col];

    int best0 = 0x7fffffff, best1 = 0x7fffffff, best2 = 0x7fffffff, best3 = 0x7fffffff;
    int bi0 = 0, bi1 = 0, bi2 = 0, bi3 = 0;
    for (int k = 0; k < KC_; ++k) {
        int d0 = 0, d1 = 0, d2 = 0, d3 = 0;
        #pragma unroll
        for (int s = 0; s < SUB_; ++s) {
            int cv = sc[k][s];                    // broadcast LDS
            int cc = s / 9, rr = (s % 9) / 3, jj = s % 3;
            d0 += w[cc][rr][jj + 0] * cv;
            d1 += w[cc][rr][jj + 1] * cv;
            d2 += w[cc][rr][jj + 2] * cv;
            d3 += w[cc][rr][jj + 3] * cv;
        }
        int y = sy[k];
        int t0 = y - 2 * d0; if (t0 < best0) { best0 = t0; bi0 = k; }
        int t1 = y - 2 * d1; if (t1 < best1) { best1 = t1; bi1 = k; }
        int t2 = y - 2 * d2; if (t2 < best2) { best2 = t2; bi2 = k; }
        int t3 = y - 2 * d3; if (t3 < best3) { best3 = t3; bi3 = k; }
    }
    int8_t* dst = g_idx + ((size_t)(b * NPIX_ + p0)) * NCB_ + c;
    dst[0]       = (int8_t)bi0;
    dst[NCB_]    = (int8_t)bi1;
    dst[2*NCB_]  = (int8_t)bi2;
    dst[3*NCB_]  = (int8_t)bi3;
}

// ---------------------------------------------------------------------------
// Kernel B: gather-accumulate 64 LUT rows per pixel (int16x2 packed adds).
// Grid (14,8,4) = 448 blocks; block = 56 pixels x 64 couts (cout quarter gz).
// Stage = 8 codebooks x 16 k x 64 couts = 16 KB = 128 rows x 128 B.
// THREE-buffer cp.async pipeline (48 KB): ONE sync per stage — the
// visibility sync for stage g also orders all gathers of stage g-1 before
// stage g+2 is issued into that buffer.
// Lane = (q = lane>>3, co8 = lane&7): LDS.128 reads a full 128 B cout row
// per 8-lane phase (conflict-free); each lane covers codebooks {2q, 2q+1}
// per stage; final merge = shfl_xor(8), shfl_xor(16) + VADD2 (exact).
// Epilogue: identical fp recipe (q==0 lanes), transpose tile in buffer 0
// (disjoint from stage 7's buffer 1), 64 cout-row stores.
// ---------------------------------------------------------------------------
__global__ void __launch_bounds__(256) out_kernel(
    const int* __restrict__ bias_q,
    const float* __restrict__ lut_s, const int* __restrict__ lut_z,
    const float* __restrict__ bias_s, const int* __restrict__ bias_z,
    const float* __restrict__ out_s, const int* __restrict__ out_z,
    float* __restrict__ out)
{
    int tile = blockIdx.x;   // 0..13
    int b    = blockIdx.y;   // 0..7
    int gz   = blockIdx.z;   // 0..3 (cout quarter)
    extern __shared__ __align__(16) char s_dyn[];              // 3 x 16 KB stages
    __shared__ __align__(16) int8_t s_idx[56 * NCB_];          // 3.5 KB
    int tid  = threadIdx.x;
    int lane = tid & 31, wg = tid >> 5;        // wg = pixel group (7 px)
    int q    = lane >> 3, co8 = lane & 7;      // codebook quarter, cout octet
    int n0   = b * NPIX_ + tile * 56;

    if (tid < 224)
        ((uint4*)s_idx)[tid] = ((const uint4*)(g_idx + (size_t)n0 * NCB_))[tid];

    // Stage issue: 16 KB = 128 rows x 8 x 16B transfers; 4 cp.async/thread.
    // Global row r of stage g lives at g_lut16 byte (g*128+r)*512 + gz*128.
    auto issue_stage = [&](int g, int buf) {
        char* sb = s_dyn + buf * 16384;
        const char* gbase = (const char*)g_lut16 + (size_t)g * 128 * 512 + gz * 128;
        #pragma unroll
        for (int j = 0; j < 4; ++j) {
            int t = tid + j * 256;
            int row = t >> 3, seg = t & 7;
            cp_async16(sb + row * 128 + seg * 16, gbase + (size_t)row * 512 + seg * 16);
        }
        cp_commit();
    };

    issue_stage(0, 0);
    issue_stage(1, 1);

    uint32_t acc[7][4];
    #pragma unroll
    for (int nl = 0; nl < 7; ++nl)
        #pragma unroll
        for (int j = 0; j < 4; ++j) acc[nl][j] = 0u;

    for (int g = 0; g < 8; ++g) {
        if (g < 7) cp_wait1(); else cp_wait0();
        __syncthreads();   // stage g visible; gathers of g-1 done block-wide
        if (g + 2 < 8) issue_stage(g + 2, (g + 2) % 3);
        const char* sb = s_dyn + (g % 3) * 16384;
        #pragma unroll
        for (int nl = 0; nl < 7; ++nl) {
            int nn = wg * 7 + nl;
            uint2 iw = *(const uint2*)(s_idx + nn * 64 + g * 8);   // 8 idx bytes
            #pragma unroll
            for (int e = 0; e < 2; ++e) {
                int cb = 2 * q + e;
                uint32_t kk = __byte_perm(iw.x, iw.y, cb) & 0xFFu;
                uint4 v = *(const uint4*)(sb + cb * 2048 + kk * 128 + co8 * 16);
                acc[nl][0] = __vadd2(acc[nl][0], v.x);
                acc[nl][1] = __vadd2(acc[nl][1], v.y);
                acc[nl][2] = __vadd2(acc[nl][2], v.z);
                acc[nl][3] = __vadd2(acc[nl][3], v.w);
            }
        }
    }

    // Merge codebook quarters (exact integer adds): q -> q^1 -> q^2
    #pragma unroll
    for (int nl = 0; nl < 7; ++nl)
        #pragma unroll
        for (int j = 0; j < 4; ++j) {
            acc[nl][j] = __vadd2(acc[nl][j], __shfl_xor_sync(0xffffffffu, acc[nl][j], 8));
            acc[nl][j] = __vadd2(acc[nl][j], __shfl_xor_sync(0xffffffffu, acc[nl][j], 16));
        }

    float ls = lut_s[0];  int lz = lut_z[0];
    float bs = bias_s[0]; int bz = bias_z[0];
    float os = out_s[0];  float ozf = (float)out_z[0];

    // q==0 lanes quantize + write transpose tile (all quarters hold full sums)
    float4* s4  = (float4*)s_dyn;            // 56*64*4 = 14336 B (buffer 0 area;
    float*  s_f = (float*)s_dyn;             // disjoint from stage-7 buffer 1)
    if (q == 0) {
        int cobase = gz * 64 + co8 * 8;
        float bd[8];
        #pragma unroll
        for (int j = 0; j < 8; ++j)
            bd[j] = __fmul_rn((float)(bias_q[cobase + j] - bz), bs);
        #pragma unroll
        for (int nl = 0; nl < 7; ++nl) {
            int nn = wg * 7 + nl;
            float f[8];
            #pragma unroll
            for (int j = 0; j < 4; ++j) {
                int Slo = (int)(short)(acc[nl][j] & 0xFFFFu);
                int Shi = ((int)acc[nl][j]) >> 16;
                #pragma unroll
                for (int e = 0; e < 2; ++e) {
                    int S = e ? Shi : Slo;
                    float sum = __fmul_rn(ls, (float)(S - 64 * lz));
                    float o   = sum + bd[2 * j + e];
                    o = fmaxf(o, 0.f);                                  // relu
                    float t = __fadd_rn(__fdiv_rn(o, os), ozf);         // true fp32 div
                    t = fminf(t, 127.f);
                    t = fmaxf(t, -128.f);
                    f[2 * j + e] = (float)__float2int_rn(t);            // half-even
                }
            }
            s4[nn * 16 + co8 * 2 + 0] = make_float4(f[0], f[1], f[2], f[3]);
            s4[nn * 16 + co8 * 2 + 1] = make_float4(f[4], f[5], f[6], f[7]);
        }
    }
    __syncthreads();
    if (tid < 64) {   // thread co owns one cout row: 56 floats, stride-64
        int co = tid;
        float v[56];
        #pragma unroll
        for (int p = 0; p < 56; ++p) v[p] = s_f[p * 64 + co];
        float4* dst = (float4*)(out + (size_t)b * COUT_ * NPIX_
                                + (gz * 64 + co) * NPIX_ + tile * 56);
        #pragma unroll
        for (int p = 0; p < 14; ++p)
            dst[p] = make_float4(v[4*p], v[4*p+1], v[4*p+2], v[4*p+3]);
    }
}

// ---------------------------------------------------------------------------
extern "C" void kernel_launch(void* const* d_in, const int* in_sizes, int n_in,
                              void* d_out, int out_size)
{
    bool alpha = (in_sizes[0] == COUT_);   // bias_q first => alphabetical (fallback)

    const int*   x_q    = (const int*)  d_in[alpha ? 11 : 0];
    const float* x_s    = (const float*)d_in[alpha ? 12 : 1];
    const int*   x_z    = (const int*)  d_in[alpha ? 13 : 2];
    const int*   cq     = (const int*)  d_in[3];
    const float* cs     = (const float*)d_in[4];
    const int*   cz     = (const int*)  d_in[5];
    const int*   lut_q  = (const int*)  d_in[6];
    const float* lut_s  = (const float*)d_in[7];
    const int*   lut_z  = (const int*)  d_in[8];
    const int*   bias_q = (const int*)  d_in[alpha ? 0 : 9];
    const float* bias_s = (const float*)d_in[alpha ? 1 : 10];
    const int*   bias_z = (const int*)  d_in[alpha ? 2 : 11];
    const float* out_s  = (const float*)d_in[alpha ? 9 : 12];
    const int*   out_z  = (const int*)  d_in[alpha ? 10 : 13];

    cudaFuncSetAttribute(out_kernel, cudaFuncAttributeMaxDynamicSharedMemorySize, 49152);

    idx_kernel<<<dim3(NCB_ + 8, B_), 256>>>(x_q, x_z, cq, cz, cs, x_s, lut_q);
    out_kernel<<<dim3(14, B_, 4), 256, 49152>>>(bias_q, lut_s, lut_z, bias_s, bias_z,
                                                out_s, out_z, (float*)d_out);
}

// round 15
// speedup vs baseline: 1.5675x; 1.5675x over previous
#include <cuda_runtime.h>
#include <cstdint>

#define B_    8
#define CIN_  128
#define H_    28
#define W_    28
#define COUT_ 256
#define NCB_  64
#define KC_   16
#define SUB_  18
#define NPIX_ 784
#define NTOT_ (B_ * NPIX_)   // 6272

// scratch (allocation-free rule: __device__ globals); 16B-aligned
__device__ __align__(16) int8_t  g_idx[NTOT_ * NCB_];           // idx[n][c], 401 KB
__device__ __align__(16) int16_t g_lut16[NCB_ * KC_ * COUT_];   // 512 KB

// ---- cp.async helpers (sm_100: LDGSTS) -----------------------------------
__device__ __forceinline__ void cp_async16(void* smem_dst, const void* gmem_src) {
    uint32_t d = (uint32_t)__cvta_generic_to_shared(smem_dst);
    asm volatile("cp.async.cg.shared.global [%0], [%1], 16;\n" :: "r"(d), "l"(gmem_src));
}
__device__ __forceinline__ void cp_commit() {
    asm volatile("cp.async.commit_group;\n");
}
__device__ __forceinline__ void cp_wait1() {
    asm volatile("cp.async.wait_group 1;\n");
}
__device__ __forceinline__ void cp_wait0() {
    asm volatile("cp.async.wait_group 0;\n");
}

// ---------------------------------------------------------------------------
// Kernel A (merged): blocks c < 64: distances + argmin via raw-byte signed
// dp4a. Compare key: y2r_k + 2*xz*sum(c_raw[k]) - 2*dot(x_raw, c_raw[k])
// (differs from true dist by a k-constant -> argmin + ties EXACTLY preserved;
//  padding cells hold xz so their (x - xz) contribution is exactly 0).
// y2r recipe bit-identical to passing version. Blocks c >= 64: lut repack.
// ---------------------------------------------------------------------------
__global__ void __launch_bounds__(256) idx_kernel(
    const int* __restrict__ xq, const int* __restrict__ xz_p,
    const int* __restrict__ cq, const int* __restrict__ cz_p,
    const float* __restrict__ cs, const float* __restrict__ xs,
    const int* __restrict__ lut_q)
{
    int c = blockIdx.x;   // codebook (or repack block if >= 64)
    int b = blockIdx.y;   // batch
    int tid = threadIdx.x;

    if (c >= NCB_) {      // ---- LUT repack: 64 blocks x 256 thr x 4 int4 ----
        int gid = ((c - NCB_) + 8 * b) * 256 + tid;   // [0, 16384)
        const int4* src = (const int4*)lut_q;         // 65536 int4
        uint2* dst = (uint2*)g_lut16;                 // 65536 uint2
        #pragma unroll
        for (int t = 0; t < 4; ++t) {
            int i = gid + t * 16384;
            int4 v = src[i];
            uint32_t lo = ((uint32_t)v.x & 0xFFFFu) | ((uint32_t)v.y << 16);
            uint32_t hi = ((uint32_t)v.z & 0xFFFFu) | ((uint32_t)v.w << 16);
            dst[i] = make_uint2(lo, hi);
        }
        return;
    }

    __shared__ int8_t  sx8[2][30][32];   // raw x_q bytes; padding = xz
    __shared__ int     sc[KC_][SUB_];    // (c_q - c_z) for y2r recipe
    __shared__ int     scp[KC_][6];      // packed raw centroids (c0,c1,c2,0)
    __shared__ int     sy[KC_];          // adjusted key base per k
    int xz = xz_p[0];
    int cz = cz_p[c];

    for (int t = tid; t < 1800; t += 256) {
        int cc  = t / 900;
        int r   = (t % 900) / 30;
        int col = t % 30;
        int ih = r - 1, iw = col - 1;
        int v = xz;                                  // padding holds xz
        if ((unsigned)ih < 28u && (unsigned)iw < 28u)
            v = xq[(((b * CIN_) + 2 * c + cc) * H_ + ih) * W_ + iw];
        sx8[cc][r][col] = (int8_t)v;
    }
    for (int t = tid; t < KC_ * SUB_; t += 256)
        sc[t / SUB_][t % SUB_] = cq[c * KC_ * SUB_ + t] - cz;
    if (tid < KC_ * 6) {                 // packed centroid rows, raw bytes
        int k = tid / 6, g = tid % 6;
        const int* q = cq + c * KC_ * SUB_ + k * SUB_ + g * 3;
        scp[k][g] = (int)( ((uint32_t)q[0] & 0xFFu)
                         | (((uint32_t)q[1] & 0xFFu) << 8)
                         | (((uint32_t)q[2] & 0xFFu) << 16) );   // byte3 = 0
    }
    __syncthreads();

    // y2r (bit-identical recipe) + key adjustment 2*xz*sum(c_raw)
    if (tid < KC_) {
        float s = cs[c];
        float acc = 0.f;
        int sum_sc = 0;
        #pragma unroll
        for (int u = 0; u < SUB_; ++u) {
            float cv = __fmul_rn((float)sc[tid][u], s);
            acc = __fmaf_rn(cv, cv, acc);
            sum_sc += sc[tid][u];
        }
        int y2r = __float2int_rn(__fdiv_rn(acc, __fmul_rn(xs[0], s)));
        int sumc_raw = sum_sc + SUB_ * cz;
        sy[tid] = y2r + 2 * xz * sumc_raw;
    }
    __syncthreads();

    if (tid >= 196) return;           // 196 threads * 4 pixels = 784
    int p0  = tid * 4;                // 4|28 -> never crosses a row
    int oh  = tid / 7;
    int ow0 = (tid % 7) * 4;

    // Build packed x windows: 6 rows (cc,r) x 4 pixels, 4 raw bytes each.
    // Row bytes [ow0, ow0+8) via two aligned LDS.32; pixel j = bytes j..j+3.
    int wrd[4][6];
    #pragma unroll
    for (int g = 0; g < 6; ++g) {
        int cc = g / 3, r = g % 3;
        const uint8_t* rowp = (const uint8_t*)&sx8[cc][oh + r][0];
        uint32_t lo = *(const uint32_t*)(rowp + ow0);
        uint32_t hi = *(const uint32_t*)(rowp + ow0 + 4);
        #pragma unroll
        for (int j = 0; j < 4; ++j)
            wrd[j][g] = (int)__funnelshift_r(lo, hi, 8 * j);
    }

    int best0 = 0x7fffffff, best1 = 0x7fffffff, best2 = 0x7fffffff, best3 = 0x7fffffff;
    int bi0 = 0, bi1 = 0, bi2 = 0, bi3 = 0;
    for (int k = 0; k < KC_; ++k) {
        int cw0 = scp[k][0], cw1 = scp[k][1], cw2 = scp[k][2];
        int cw3 = scp[k][3], cw4 = scp[k][4], cw5 = scp[k][5];
        int y = sy[k];
        int d0 = 0, d1 = 0, d2 = 0, d3 = 0;
        d0 = __dp4a(wrd[0][0], cw0, d0); d1 = __dp4a(wrd[1][0], cw0, d1);
        d2 = __dp4a(wrd[2][0], cw0, d2); d3 = __dp4a(wrd[3][0], cw0, d3);
        d0 = __dp4a(wrd[0][1], cw1, d0); d1 = __dp4a(wrd[1][1], cw1, d1);
        d2 = __dp4a(wrd[2][1], cw1, d2); d3 = __dp4a(wrd[3][1], cw1, d3);
        d0 = __dp4a(wrd[0][2], cw2, d0); d1 = __dp4a(wrd[1][2], cw2, d1);
        d2 = __dp4a(wrd[2][2], cw2, d2); d3 = __dp4a(wrd[3][2], cw2, d3);
        d0 = __dp4a(wrd[0][3], cw3, d0); d1 = __dp4a(wrd[1][3], cw3, d1);
        d2 = __dp4a(wrd[2][3], cw3, d2); d3 = __dp4a(wrd[3][3], cw3, d3);
        d0 = __dp4a(wrd[0][4], cw4, d0); d1 = __dp4a(wrd[1][4], cw4, d1);
        d2 = __dp4a(wrd[2][4], cw4, d2); d3 = __dp4a(wrd[3][4], cw4, d3);
        d0 = __dp4a(wrd[0][5], cw5, d0); d1 = __dp4a(wrd[1][5], cw5, d1);
        d2 = __dp4a(wrd[2][5], cw5, d2); d3 = __dp4a(wrd[3][5], cw5, d3);
        int t0 = y - 2 * d0; if (t0 < best0) { best0 = t0; bi0 = k; }
        int t1 = y - 2 * d1; if (t1 < best1) { best1 = t1; bi1 = k; }
        int t2 = y - 2 * d2; if (t2 < best2) { best2 = t2; bi2 = k; }
        int t3 = y - 2 * d3; if (t3 < best3) { best3 = t3; bi3 = k; }
    }
    int8_t* dst = g_idx + ((size_t)(b * NPIX_ + p0)) * NCB_ + c;
    dst[0]       = (int8_t)bi0;
    dst[NCB_]    = (int8_t)bi1;
    dst[2*NCB_]  = (int8_t)bi2;
    dst[3*NCB_]  = (int8_t)bi3;
}

// ---------------------------------------------------------------------------
// Kernel B: EXACT round-12 passing version (26.9 us). Gather-accumulate 64
// LUT rows per pixel; grid (14,8,4); cp.async double-buffered 16 KB stages;
// lane = (h, co4); LDS.64 gather; shfl_xor(16) merge; identical fp recipe.
// ---------------------------------------------------------------------------
__global__ void __launch_bounds__(256) out_kernel(
    const int* __restrict__ bias_q,
    const float* __restrict__ lut_s, const int* __restrict__ lut_z,
    const float* __restrict__ bias_s, const int* __restrict__ bias_z,
    const float* __restrict__ out_s, const int* __restrict__ out_z,
    float* __restrict__ out)
{
    int tile = blockIdx.x;   // 0..13
    int b    = blockIdx.y;   // 0..7
    int gz   = blockIdx.z;   // 0..3 (cout quarter)
    extern __shared__ __align__(16) char s_dyn[];              // 2 x 16 KB stages
    __shared__ __align__(16) int8_t s_idx[56 * NCB_];          // 3.5 KB
    int tid  = threadIdx.x;
    int lane = tid & 31, wg = tid >> 5;        // wg = pixel group (7 px)
    int h    = lane >> 4, co4 = lane & 15;     // codebook half, cout quad
    int n0   = b * NPIX_ + tile * 56;

    if (tid < 224)
        ((uint4*)s_idx)[tid] = ((const uint4*)(g_idx + (size_t)n0 * NCB_))[tid];

    auto issue_stage = [&](int g, int buf) {
        char* sb = s_dyn + buf * 16384;
        const char* gbase = (const char*)g_lut16 + (size_t)g * 128 * 512 + gz * 128;
        #pragma unroll
        for (int j = 0; j < 4; ++j) {
            int t = tid + j * 256;
            int row = t >> 3, seg = t & 7;     // 128 rows x 8 x 16B
            cp_async16(sb + row * 128 + seg * 16, gbase + (size_t)row * 512 + seg * 16);
        }
        cp_commit();
    };

    issue_stage(0, 0);

    uint32_t acc[7][2];
    #pragma unroll
    for (int nl = 0; nl < 7; ++nl) { acc[nl][0] = 0u; acc[nl][1] = 0u; }

    for (int g = 0; g < 8; ++g) {
        if (g < 7) issue_stage(g + 1, (g + 1) & 1);
        if (g < 7) cp_wait1(); else cp_wait0();
        __syncthreads();                     // stage g visible block-wide
        const char* sb = s_dyn + (g & 1) * 16384;
        #pragma unroll
        for (int nl = 0; nl < 7; ++nl) {
            int nn = wg * 7 + nl;
            uint2 iw = *(const uint2*)(s_idx + nn * 64 + g * 8);   // 8 idx bytes
            #pragma unroll
            for (int cc = 0; cc < 4; ++cc) {
                uint32_t kk = __byte_perm(iw.x, iw.y, 2 * cc + h) & 0xFFu;
                uint2 v = *(const uint2*)(sb + (2 * cc + h) * 2048 + kk * 128 + co4 * 8);
                acc[nl][0] = __vadd2(acc[nl][0], v.x);
                acc[nl][1] = __vadd2(acc[nl][1], v.y);
            }
        }
        __syncthreads();                     // gathers done before buffer reuse
    }

    #pragma unroll
    for (int nl = 0; nl < 7; ++nl) {
        acc[nl][0] = __vadd2(acc[nl][0], __shfl_xor_sync(0xffffffffu, acc[nl][0], 16));
        acc[nl][1] = __vadd2(acc[nl][1], __shfl_xor_sync(0xffffffffu, acc[nl][1], 16));
    }

    float ls = lut_s[0];  int lz = lut_z[0];
    float bs = bias_s[0]; int bz = bias_z[0];
    float os = out_s[0];  float ozf = (float)out_z[0];

    float4* s4  = (float4*)s_dyn;            // 56*64*4 = 14336 B (buffer 0 area)
    float*  s_f = (float*)s_dyn;
    if (h == 0) {
        int cobase = gz * 64 + co4 * 4;
        float bd[4];
        #pragma unroll
        for (int j = 0; j < 4; ++j)
            bd[j] = __fmul_rn((float)(bias_q[cobase + j] - bz), bs);
        #pragma unroll
        for (int nl = 0; nl < 7; ++nl) {
            int nn = wg * 7 + nl;
            float f[4];
            #pragma unroll
            for (int j = 0; j < 4; ++j) {
                int S = (j & 1) ? (((int)acc[nl][j >> 1]) >> 16)
                                : ((int)(short)(acc[nl][j >> 1] & 0xFFFFu));
                float sum = __fmul_rn(ls, (float)(S - 64 * lz));
                float o   = sum + bd[j];
                o = fmaxf(o, 0.f);                                  // relu
                float t = __fadd_rn(__fdiv_rn(o, os), ozf);         // true fp32 div
                t = fminf(t, 127.f);
                t = fmaxf(t, -128.f);
                f[j] = (float)__float2int_rn(t);                    // half-even
            }
            s4[nn * 16 + co4] = make_float4(f[0], f[1], f[2], f[3]);
        }
    }
    __syncthreads();
    if (tid < 64) {   // thread co owns one cout row: 56 floats, stride-64
        int co = tid;
        float v[56];
        #pragma unroll
        for (int p = 0; p < 56; ++p) v[p] = s_f[p * 64 + co];
        float4* dst = (float4*)(out + (size_t)b * COUT_ * NPIX_
                                + (gz * 64 + co) * NPIX_ + tile * 56);
        #pragma unroll
        for (int p = 0; p < 14; ++p)
            dst[p] = make_float4(v[4*p], v[4*p+1], v[4*p+2], v[4*p+3]);
    }
}

// ---------------------------------------------------------------------------
extern "C" void kernel_launch(void* const* d_in, const int* in_sizes, int n_in,
                              void* d_out, int out_size)
{
    bool alpha = (in_sizes[0] == COUT_);   // bias_q first => alphabetical (fallback)

    const int*   x_q    = (const int*)  d_in[alpha ? 11 : 0];
    const float* x_s    = (const float*)d_in[alpha ? 12 : 1];
    const int*   x_z    = (const int*)  d_in[alpha ? 13 : 2];
    const int*   cq     = (const int*)  d_in[3];
    const float* cs     = (const float*)d_in[4];
    const int*   cz     = (const int*)  d_in[5];
    const int*   lut_q  = (const int*)  d_in[6];
    const float* lut_s  = (const float*)d_in[7];
    const int*   lut_z  = (const int*)  d_in[8];
    const int*   bias_q = (const int*)  d_in[alpha ? 0 : 9];
    const float* bias_s = (const float*)d_in[alpha ? 1 : 10];
    const int*   bias_z = (const int*)  d_in[alpha ? 2 : 11];
    const float* out_s  = (const float*)d_in[alpha ? 9 : 12];
    const int*   out_z  = (const int*)  d_in[alpha ? 10 : 13];

    cudaFuncSetAttribute(out_kernel, cudaFuncAttributeMaxDynamicSharedMemorySize, 32768);

    idx_kernel<<<dim3(NCB_ + 8, B_), 256>>>(x_q, x_z, cq, cz, cs, x_s, lut_q);
    out_kernel<<<dim3(14, B_, 4), 256, 32768>>>(bias_q, lut_s, lut_z, bias_s, bias_z,
                                                out_s, out_z, (float*)d_out);
}